// round 1
// baseline (speedup 1.0000x reference)
#include <cuda_runtime.h>
#include <cstdint>

// Problem constants
#define HW    4096
#define CH    256
#define BATCH 4
// sizes
//  per-side activation: BATCH*HW*CH = 4*4096*256 = 1<<22 floats
//  per (side,b) score matrix: HW*HW = 1<<24 floats

__device__ float g_xln[2ull * BATCH * HW * CH];
__device__ float g_q  [2ull * BATCH * HW * CH];
__device__ float g_k  [2ull * BATCH * HW * CH];
__device__ float g_v  [2ull * BATCH * HW * CH];
__device__ float g_o  [2ull * BATCH * HW * CH];
__device__ float g_e  [2ull * BATCH * HW * HW];   // 537 MB
__device__ float g_invd[2ull * HW * HW];          // 134 MB

// ---------------------------------------------------------------------------
// Kernel 1: LayerNorm over channel dim with transpose (B,C,HW)->(B,HW,C)
// grid: (HW/32, BATCH), block 256
// ---------------------------------------------------------------------------
__global__ __launch_bounds__(256) void ln_kernel(const float* __restrict__ x,
                                                 const float* __restrict__ gm,
                                                 const float* __restrict__ bt,
                                                 int side) {
    int b  = blockIdx.y;
    int p0 = blockIdx.x << 5;
    int tid = threadIdx.x, lane = tid & 31, warp = tid >> 5;

    __shared__ float tile[CH][33];
    __shared__ float red[2][8][32];
    __shared__ float mu_s[32], rs_s[32];

    // coalesced load: each warp loads 32 channel rows of 32 consecutive p
    #pragma unroll 4
    for (int i = 0; i < 32; i++) {
        int c = (warp << 5) + i;
        tile[c][lane] = x[((size_t)b * CH + c) * HW + p0 + lane];
    }
    __syncthreads();

    // per-p mean/var: 8 segments of 32 channels each
    {
        int pl = tid & 31, seg = tid >> 5;
        float s = 0.f, s2 = 0.f;
        #pragma unroll 8
        for (int c = seg * 32; c < seg * 32 + 32; c++) {
            float v = tile[c][pl];
            s += v; s2 += v * v;
        }
        red[0][seg][pl] = s;
        red[1][seg][pl] = s2;
    }
    __syncthreads();
    if (tid < 32) {
        float S = 0.f, S2 = 0.f;
        #pragma unroll
        for (int g = 0; g < 8; g++) { S += red[0][g][tid]; S2 += red[1][g][tid]; }
        float mu  = S * (1.f / 256.f);
        float var = S2 * (1.f / 256.f) - mu * mu;
        mu_s[tid] = mu;
        rs_s[tid] = rsqrtf(var + 1e-5f);
    }
    __syncthreads();

    float* xln = g_xln + ((size_t)side << 22);
    #pragma unroll
    for (int pp = warp * 4; pp < warp * 4 + 4; pp++) {
        float mu = mu_s[pp], rs = rs_s[pp];
        #pragma unroll
        for (int c = lane; c < CH; c += 32) {
            float v = (tile[c][pp] - mu) * rs * gm[c] + bt[c];
            xln[((size_t)(b * HW + p0 + pp)) * CH + c] = v;
        }
    }
}

// ---------------------------------------------------------------------------
// Kernel 2: QKV projection GEMM  C(16384x256) = A(16384x256) @ W(256x256)
// grid: (4, 256), block 256.  which: 0=Q 1=K 2=V
// ---------------------------------------------------------------------------
__global__ __launch_bounds__(256) void gemm_qkv(const float* __restrict__ W,
                                                int side, int which) {
    const float* A = g_xln + ((size_t)side << 22);
    float* C = (which == 0 ? g_q : which == 1 ? g_k : g_v) + ((size_t)side << 22);

    int m0 = blockIdx.y << 6, n0 = blockIdx.x << 6;
    __shared__ float As[16][64], Bs[16][64];
    int tid = threadIdx.x;
    int ar = tid >> 2, ac = (tid & 3) << 2;      // A-tile load map (64x16)
    int br = tid >> 4, bc = (tid & 15) << 2;     // B-tile load map (16x64)
    int tx = tid & 15, ty = tid >> 4;

    float acc[4][4] = {};
    for (int k0 = 0; k0 < 256; k0 += 16) {
        float4 av = *(const float4*)(A + (size_t)(m0 + ar) * 256 + k0 + ac);
        float4 bv = *(const float4*)(W + (size_t)(k0 + br) * 256 + n0 + bc);
        __syncthreads();
        As[ac + 0][ar] = av.x; As[ac + 1][ar] = av.y;
        As[ac + 2][ar] = av.z; As[ac + 3][ar] = av.w;
        *(float4*)&Bs[br][bc] = bv;
        __syncthreads();
        #pragma unroll
        for (int k = 0; k < 16; k++) {
            float4 a = *(const float4*)&As[k][ty << 2];
            float4 b = *(const float4*)&Bs[k][tx << 2];
            float aa[4] = {a.x, a.y, a.z, a.w};
            float bb[4] = {b.x, b.y, b.z, b.w};
            #pragma unroll
            for (int i = 0; i < 4; i++)
                #pragma unroll
                for (int j = 0; j < 4; j++)
                    acc[i][j] += aa[i] * bb[j];
        }
    }
    #pragma unroll
    for (int i = 0; i < 4; i++) {
        float4 r = make_float4(acc[i][0], acc[i][1], acc[i][2], acc[i][3]);
        *(float4*)(C + (size_t)(m0 + (ty << 2) + i) * 256 + n0 + (tx << 2)) = r;
    }
}

// ---------------------------------------------------------------------------
// Kernel 3: scores  E[side,b,n,m] = exp(scale * dot(Q[side,b,n,:], K[side^1,b,m,:]))
// NT GEMM, M=N=4096, K=256.  grid: (64, 64, 8), z = side*4+b
// ---------------------------------------------------------------------------
__global__ __launch_bounds__(256) void gemm_scores() {
    int z = blockIdx.z;
    int side = z >> 2, b = z & 3;
    const float* Aq = g_q + (((size_t)side * 4 + b) << 20);
    const float* Bk = g_k + (((size_t)(side ^ 1) * 4 + b) << 20);
    float*       Ce = g_e + ((size_t)z << 24);

    int m0 = blockIdx.y << 6, n0 = blockIdx.x << 6;
    __shared__ float As[16][64], Bs[16][64];
    int tid = threadIdx.x;
    int ar = tid >> 2, ac = (tid & 3) << 2;
    int tx = tid & 15, ty = tid >> 4;

    const float* aptr = Aq + (size_t)(m0 + ar) * 256 + ac;
    const float* bptr = Bk + (size_t)(n0 + ar) * 256 + ac;

    float acc[4][4] = {};
    for (int k0 = 0; k0 < 256; k0 += 16) {
        float4 av = *(const float4*)(aptr + k0);
        float4 bv = *(const float4*)(bptr + k0);
        __syncthreads();
        As[ac + 0][ar] = av.x; As[ac + 1][ar] = av.y;
        As[ac + 2][ar] = av.z; As[ac + 3][ar] = av.w;
        Bs[ac + 0][ar] = bv.x; Bs[ac + 1][ar] = bv.y;
        Bs[ac + 2][ar] = bv.z; Bs[ac + 3][ar] = bv.w;
        __syncthreads();
        #pragma unroll
        for (int k = 0; k < 16; k++) {
            float4 a = *(const float4*)&As[k][ty << 2];
            float4 b4 = *(const float4*)&Bs[k][tx << 2];
            float aa[4] = {a.x, a.y, a.z, a.w};
            float bb[4] = {b4.x, b4.y, b4.z, b4.w};
            #pragma unroll
            for (int i = 0; i < 4; i++)
                #pragma unroll
                for (int j = 0; j < 4; j++)
                    acc[i][j] += aa[i] * bb[j];
        }
    }
    const float scale = 0.0625f;  // 1/sqrt(256)
    #pragma unroll
    for (int i = 0; i < 4; i++) {
        float4 r;
        r.x = __expf(acc[i][0] * scale);
        r.y = __expf(acc[i][1] * scale);
        r.z = __expf(acc[i][2] * scale);
        r.w = __expf(acc[i][3] * scale);
        *(float4*)(Ce + (size_t)(m0 + (ty << 2) + i) * HW + n0 + (tx << 2)) = r;
    }
}

// ---------------------------------------------------------------------------
// Kernel 4: invD[side,n,m] = 1 / sum_b E[side,b,n,m]
// grid: 2*HW*HW/256 = 131072 blocks
// ---------------------------------------------------------------------------
__global__ __launch_bounds__(256) void invd_kernel() {
    size_t i = (size_t)blockIdx.x * 256 + threadIdx.x;
    size_t side = i >> 24;
    size_t nm = i & 0xFFFFFFull;
    const float* e = g_e + side * (4ull << 24) + nm;
    float s = e[0] + e[1ull << 24] + e[2ull << 24] + e[3ull << 24];
    g_invd[i] = 1.0f / s;
}

// ---------------------------------------------------------------------------
// Kernel 5: O[side,b] = (E[side,b] * invD[side]) @ V[side,b]
// NN GEMM, M=4096, N=256, K=4096.  grid: (4, 64, 8)
// ---------------------------------------------------------------------------
__global__ __launch_bounds__(256) void gemm_pv() {
    int z = blockIdx.z;
    int side = z >> 2;
    const float* Ae = g_e    + ((size_t)z << 24);
    const float* Dv = g_invd + ((size_t)side << 24);
    const float* Bv = g_v    + ((size_t)z << 20);
    float*       Co = g_o    + ((size_t)z << 20);

    int m0 = blockIdx.y << 6, n0 = blockIdx.x << 6;
    __shared__ float As[16][64], Bs[16][64];
    int tid = threadIdx.x;
    int ar = tid >> 2, ac = (tid & 3) << 2;
    int br = tid >> 4, bc = (tid & 15) << 2;
    int tx = tid & 15, ty = tid >> 4;

    float acc[4][4] = {};
    for (int k0 = 0; k0 < HW; k0 += 16) {
        size_t aoff = (size_t)(m0 + ar) * HW + k0 + ac;
        float4 av = *(const float4*)(Ae + aoff);
        float4 dv = *(const float4*)(Dv + aoff);
        av.x *= dv.x; av.y *= dv.y; av.z *= dv.z; av.w *= dv.w;
        float4 bv = *(const float4*)(Bv + (size_t)(k0 + br) * 256 + n0 + bc);
        __syncthreads();
        As[ac + 0][ar] = av.x; As[ac + 1][ar] = av.y;
        As[ac + 2][ar] = av.z; As[ac + 3][ar] = av.w;
        *(float4*)&Bs[br][bc] = bv;
        __syncthreads();
        #pragma unroll
        for (int k = 0; k < 16; k++) {
            float4 a = *(const float4*)&As[k][ty << 2];
            float4 b4 = *(const float4*)&Bs[k][tx << 2];
            float aa[4] = {a.x, a.y, a.z, a.w};
            float bb[4] = {b4.x, b4.y, b4.z, b4.w};
            #pragma unroll
            for (int i = 0; i < 4; i++)
                #pragma unroll
                for (int j = 0; j < 4; j++)
                    acc[i][j] += aa[i] * bb[j];
        }
    }
    #pragma unroll
    for (int i = 0; i < 4; i++) {
        float4 r = make_float4(acc[i][0], acc[i][1], acc[i][2], acc[i][3]);
        *(float4*)(Co + (size_t)(m0 + (ty << 2) + i) * 256 + n0 + (tx << 2)) = r;
    }
}

// ---------------------------------------------------------------------------
// Kernel 6: out[b,c,p] = x[b,c,p] + (O @ Wo)[b,p,c]   (transpose + residual)
// NN GEMM, M=16384, N=256, K=256.  grid: (4, 256)
// ---------------------------------------------------------------------------
__global__ __launch_bounds__(256) void gemm_out(const float* __restrict__ Wo,
                                                const float* __restrict__ x,
                                                float* __restrict__ outp,
                                                int side) {
    const float* A = g_o + ((size_t)side << 22);

    int m0 = blockIdx.y << 6, n0 = blockIdx.x << 6;
    __shared__ float As[16][64], Bs[16][64];
    __shared__ float cs[64][65];
    int tid = threadIdx.x;
    int ar = tid >> 2, ac = (tid & 3) << 2;
    int br = tid >> 4, bc = (tid & 15) << 2;
    int tx = tid & 15, ty = tid >> 4;

    float acc[4][4] = {};
    for (int k0 = 0; k0 < 256; k0 += 16) {
        float4 av = *(const float4*)(A + (size_t)(m0 + ar) * 256 + k0 + ac);
        float4 bv = *(const float4*)(Wo + (size_t)(k0 + br) * 256 + n0 + bc);
        __syncthreads();
        As[ac + 0][ar] = av.x; As[ac + 1][ar] = av.y;
        As[ac + 2][ar] = av.z; As[ac + 3][ar] = av.w;
        *(float4*)&Bs[br][bc] = bv;
        __syncthreads();
        #pragma unroll
        for (int k = 0; k < 16; k++) {
            float4 a = *(const float4*)&As[k][ty << 2];
            float4 b4 = *(const float4*)&Bs[k][tx << 2];
            float aa[4] = {a.x, a.y, a.z, a.w};
            float bb[4] = {b4.x, b4.y, b4.z, b4.w};
            #pragma unroll
            for (int i = 0; i < 4; i++)
                #pragma unroll
                for (int j = 0; j < 4; j++)
                    acc[i][j] += aa[i] * bb[j];
        }
    }
    // stage tile transposed: cs[c_local][p_local]
    __syncthreads();
    #pragma unroll
    for (int i = 0; i < 4; i++)
        #pragma unroll
        for (int j = 0; j < 4; j++)
            cs[(tx << 2) + j][(ty << 2) + i] = acc[i][j];
    __syncthreads();

    int bb2 = m0 >> 12;        // batch index (tiles never straddle batch: 4096%64==0)
    int p0  = m0 & 4095;
    for (int idx = tid; idx < 64 * 64; idx += 256) {
        int cl = idx >> 6, pl = idx & 63;
        size_t off = ((size_t)bb2 * CH + (n0 + cl)) * HW + (p0 + pl);
        outp[off] = x[off] + cs[cl][pl];
    }
}

// ---------------------------------------------------------------------------
extern "C" void kernel_launch(void* const* d_in, const int* in_sizes, int n_in,
                              void* d_out, int out_size) {
    const float* x_l = (const float*)d_in[0];
    const float* x_r = (const float*)d_in[1];
    const float* Wq  = (const float*)d_in[2];
    const float* Wk  = (const float*)d_in[3];
    const float* Wv  = (const float*)d_in[4];
    const float* Wo  = (const float*)d_in[5];
    const float* g1  = (const float*)d_in[6];
    const float* b1  = (const float*)d_in[7];
    const float* g2  = (const float*)d_in[8];
    const float* b2  = (const float*)d_in[9];
    float* out = (float*)d_out;

    // 1) LayerNorm + transpose
    ln_kernel<<<dim3(HW / 32, BATCH), 256>>>(x_l, g1, b1, 0);
    ln_kernel<<<dim3(HW / 32, BATCH), 256>>>(x_r, g2, b2, 1);

    // 2) QKV projections (6 GEMMs)
    for (int side = 0; side < 2; side++) {
        gemm_qkv<<<dim3(4, 256), 256>>>(Wq, side, 0);
        gemm_qkv<<<dim3(4, 256), 256>>>(Wk, side, 1);
        gemm_qkv<<<dim3(4, 256), 256>>>(Wv, side, 2);
    }

    // 3) E = exp(scale * Q @ K^T)  (cross-side K)
    gemm_scores<<<dim3(64, 64, 8), 256>>>();

    // 4) invD = 1 / sum_b E
    invd_kernel<<<131072, 256>>>();

    // 5) O = (E * invD) @ V
    gemm_pv<<<dim3(4, 64, 8), 256>>>();

    // 6) out = x + (O @ Wo)^T  (transpose back to (B,C,H,W))
    gemm_out<<<dim3(4, 256), 256>>>(Wo, x_l, out, 0);
    gemm_out<<<dim3(4, 256), 256>>>(Wo, x_r, out + (size_t)BATCH * CH * HW, 1);
}

// round 3
// speedup vs baseline: 4.5355x; 4.5355x over previous
#include <cuda_runtime.h>
#include <cuda_fp16.h>
#include <cstdint>

#define HW    4096
#define CH    256
#define BATCH 4

// fp16 activations / operands
__device__ __half g_xh [2ull * BATCH * HW * CH];          // LN output [side][p][c]
__device__ __half g_wh [768ull * 256];                    // [Wq|Wk|Wv]^T: [n][k]
__device__ __half g_qh [2ull * BATCH * HW * CH];          // [z][p][c]
__device__ __half g_kh [2ull * BATCH * HW * CH];          // [z][p][c]
__device__ __half g_vth[2ull * BATCH * HW * CH];          // V^T: [z][c][m]
__device__ __half g_eh [2ull * BATCH * HW * HW];          // E then P (in-place), 268MB
__device__ float  g_o  [2ull * BATCH * HW * CH];          // PV output fp32

// ---------------------------------------------------------------------------
// mma.sync m16n8k16 fp16 -> fp32
// ---------------------------------------------------------------------------
__device__ __forceinline__ void mma16816(float (&c)[4], const uint32_t (&a)[4],
                                         const uint32_t (&b)[2]) {
    asm volatile(
        "mma.sync.aligned.m16n8k16.row.col.f32.f16.f16.f32 "
        "{%0,%1,%2,%3}, {%4,%5,%6,%7}, {%8,%9}, {%0,%1,%2,%3};"
        : "+f"(c[0]), "+f"(c[1]), "+f"(c[2]), "+f"(c[3])
        : "r"(a[0]), "r"(a[1]), "r"(a[2]), "r"(a[3]), "r"(b[0]), "r"(b[1]));
}

// ---------------------------------------------------------------------------
// Shared GEMM core: CTA tile 128x128, k-chunk 32 halfs, double-buffered smem.
// 256 threads = 8 warps (2m x 4n), warp tile 64x32, m16n8k16 fragments.
// smem: 2 stages x (A 128x40 + B 128x40) halfs = 40960 bytes.
// ---------------------------------------------------------------------------
template <int NCH>
__device__ __forceinline__ void gemm_core(const __half* __restrict__ Ag,
                                          const __half* __restrict__ Bg,
                                          size_t ldA, size_t ldB,
                                          __half* sm, float (&acc)[4][4][4]) {
    const int tid = threadIdx.x;
    const int wid = tid >> 5, lane = tid & 31;
    const int wm = wid >> 2, wn = wid & 3;
    const int qr = lane >> 2, qc = lane & 3;
    const int ar = tid >> 2, acg = tid & 3;

    __half* As[2] = { sm,        sm + 10240 };
    __half* Bs[2] = { sm + 5120, sm + 15360 };

    uint4 ra0, ra1, rb0, rb1;

    auto LDG = [&](int c) {
        const __half* ap = Ag + (size_t)ar * ldA + (size_t)c * 32 + acg * 8;
        ra0 = *(const uint4*)ap;
        ra1 = *(const uint4*)(ap + 64 * ldA);
        const __half* bp = Bg + (size_t)ar * ldB + (size_t)c * 32 + acg * 8;
        rb0 = *(const uint4*)bp;
        rb1 = *(const uint4*)(bp + 64 * ldB);
    };
    auto STS = [&](int s) {
        *(uint4*)(As[s] + ar * 40 + acg * 8)        = ra0;
        *(uint4*)(As[s] + (ar + 64) * 40 + acg * 8) = ra1;
        *(uint4*)(Bs[s] + ar * 40 + acg * 8)        = rb0;
        *(uint4*)(Bs[s] + (ar + 64) * 40 + acg * 8) = rb1;
    };

    LDG(0); STS(0);
    if (NCH > 1) LDG(1);
    __syncthreads();

    #pragma unroll 1
    for (int c = 0; c < NCH; c++) {
        const int s = c & 1;
        if (c + 1 < NCH) {
            STS(s ^ 1);
            if (c + 2 < NCH) LDG(c + 2);
        }
        #pragma unroll
        for (int ks = 0; ks < 2; ks++) {
            uint32_t af[4][4], bf[4][2];
            #pragma unroll
            for (int i = 0; i < 4; i++) {
                const __half* p = As[s] + (wm * 64 + i * 16 + qr) * 40 + ks * 16 + qc * 2;
                af[i][0] = *(const uint32_t*)p;
                af[i][1] = *(const uint32_t*)(p + 8 * 40);
                af[i][2] = *(const uint32_t*)(p + 8);
                af[i][3] = *(const uint32_t*)(p + 8 * 40 + 8);
            }
            #pragma unroll
            for (int j = 0; j < 4; j++) {
                const __half* p = Bs[s] + (wn * 32 + j * 8 + qr) * 40 + ks * 16 + qc * 2;
                bf[j][0] = *(const uint32_t*)p;
                bf[j][1] = *(const uint32_t*)(p + 8);
            }
            #pragma unroll
            for (int i = 0; i < 4; i++)
                #pragma unroll
                for (int j = 0; j < 4; j++)
                    mma16816(acc[i][j], af[i], bf[j]);
        }
        __syncthreads();
    }
}

#define SMEM_MMA 40960

// ---------------------------------------------------------------------------
// Kernel 1: LayerNorm over channels with transpose -> fp16 [side][p][c]
// ---------------------------------------------------------------------------
__global__ __launch_bounds__(256) void ln_kernel(const float* __restrict__ x,
                                                 const float* __restrict__ gm,
                                                 const float* __restrict__ bt,
                                                 int side) {
    int b  = blockIdx.y;
    int p0 = blockIdx.x << 5;
    int tid = threadIdx.x, lane = tid & 31, warp = tid >> 5;

    __shared__ float tile[CH][33];
    __shared__ float red[2][8][32];
    __shared__ float mu_s[32], rs_s[32];

    #pragma unroll 4
    for (int i = 0; i < 32; i++) {
        int c = (warp << 5) + i;
        tile[c][lane] = x[((size_t)b * CH + c) * HW + p0 + lane];
    }
    __syncthreads();

    {
        int pl = tid & 31, seg = tid >> 5;
        float s = 0.f, s2 = 0.f;
        #pragma unroll 8
        for (int c = seg * 32; c < seg * 32 + 32; c++) {
            float v = tile[c][pl];
            s += v; s2 += v * v;
        }
        red[0][seg][pl] = s;
        red[1][seg][pl] = s2;
    }
    __syncthreads();
    if (tid < 32) {
        float S = 0.f, S2 = 0.f;
        #pragma unroll
        for (int g = 0; g < 8; g++) { S += red[0][g][tid]; S2 += red[1][g][tid]; }
        float mu  = S * (1.f / 256.f);
        float var = S2 * (1.f / 256.f) - mu * mu;
        mu_s[tid] = mu;
        rs_s[tid] = rsqrtf(var + 1e-5f);
    }
    __syncthreads();

    __half* xh = g_xh + ((size_t)side << 22);
    #pragma unroll
    for (int pp = warp * 4; pp < warp * 4 + 4; pp++) {
        float mu = mu_s[pp], rs = rs_s[pp];
        #pragma unroll
        for (int c = lane; c < CH; c += 32) {
            float v = (tile[c][pp] - mu) * rs * gm[c] + bt[c];
            xh[((size_t)(b * HW + p0 + pp)) * 256 + c] = __float2half_rn(v);
        }
    }
}

// ---------------------------------------------------------------------------
// Kernel 2: weight transpose+convert: g_wh[n][k] = W_which[k][n]
// ---------------------------------------------------------------------------
__global__ __launch_bounds__(256) void wconv_kernel(const float* __restrict__ Wq,
                                                    const float* __restrict__ Wk,
                                                    const float* __restrict__ Wv) {
    int n = blockIdx.x, k = threadIdx.x;
    const float* W = (n < 256) ? Wq : (n < 512) ? Wk : Wv;
    g_wh[(size_t)n * 256 + k] = __float2half_rn(W[(size_t)k * 256 + (n & 255)]);
}

// ---------------------------------------------------------------------------
// Kernel 3: fused QKV GEMM. grid (6, 128, 2). N: [0,256)Q [256,512)K [512,768)V
// ---------------------------------------------------------------------------
__global__ __launch_bounds__(256, 2) void qkv_mma() {
    extern __shared__ __half sm[];
    const int side = blockIdx.z;
    const int m0 = blockIdx.y << 7, n0 = blockIdx.x << 7;

    const __half* Ag = g_xh + ((size_t)side << 22) + (size_t)m0 * 256;
    const __half* Bg = g_wh + (size_t)n0 * 256;

    float acc[4][4][4] = {};
    gemm_core<8>(Ag, Bg, 256, 256, sm, acc);

    const int tid = threadIdx.x, wid = tid >> 5, lane = tid & 31;
    const int wm = wid >> 2, wn = wid & 3;
    const int qr = lane >> 2, qc = lane & 3;

    const int z = side * 4 + (m0 >> 12);
    const int pb = m0 & 4095;

    if (n0 < 512) {
        __half* dst = ((n0 >> 8) == 0 ? g_qh : g_kh) + ((size_t)z << 20);
        const int nloc = n0 & 255;
        #pragma unroll
        for (int i = 0; i < 4; i++) {
            int p = pb + wm * 64 + i * 16 + qr;
            #pragma unroll
            for (int j = 0; j < 4; j++) {
                int col = nloc + wn * 32 + j * 8 + qc * 2;
                *(uint32_t*)(dst + (size_t)p * 256 + col) =
                    __half2_raw(__floats2half2_rn(acc[i][j][0], acc[i][j][1])).x |
                    ((uint32_t)__half2_raw(__floats2half2_rn(acc[i][j][0], acc[i][j][1])).y << 16);
                *(uint32_t*)(dst + (size_t)(p + 8) * 256 + col) =
                    __half2_raw(__floats2half2_rn(acc[i][j][2], acc[i][j][3])).x |
                    ((uint32_t)__half2_raw(__floats2half2_rn(acc[i][j][2], acc[i][j][3])).y << 16);
            }
        }
    } else {
        // V: transpose via smem -> g_vth[z][c][m]
        __syncthreads();
        __half* st = sm;   // [128 n][136 m]
        #pragma unroll
        for (int i = 0; i < 4; i++) {
            int ml = wm * 64 + i * 16 + qr;
            #pragma unroll
            for (int j = 0; j < 4; j++) {
                int nl = wn * 32 + j * 8 + qc * 2;
                st[(size_t)nl * 136 + ml]           = __float2half_rn(acc[i][j][0]);
                st[(size_t)(nl + 1) * 136 + ml]     = __float2half_rn(acc[i][j][1]);
                st[(size_t)nl * 136 + ml + 8]       = __float2half_rn(acc[i][j][2]);
                st[(size_t)(nl + 1) * 136 + ml + 8] = __float2half_rn(acc[i][j][3]);
            }
        }
        __syncthreads();
        const int cv0 = n0 - 512;
        __half* dst = g_vth + ((size_t)z << 20) + pb;
        for (int idx = tid; idx < 128 * 16; idx += 256) {
            int r = idx >> 4, g = idx & 15;
            uint4 v = *(const uint4*)(st + (size_t)r * 136 + g * 8);
            *(uint4*)(dst + (size_t)(cv0 + r) * 4096 + g * 8) = v;
        }
    }
}

// ---------------------------------------------------------------------------
// Kernel 4: scores  E[z,m,n] = exp(scale * Q[z][m] . K[z'][n]) -> fp16
// grid (32, 32, 8)
// ---------------------------------------------------------------------------
__global__ __launch_bounds__(256, 2) void scores_mma() {
    extern __shared__ __half sm[];
    const int z = blockIdx.z;
    const int zk = ((z >> 2) ^ 1) * 4 + (z & 3);
    const int m0 = blockIdx.y << 7, n0 = blockIdx.x << 7;

    const __half* Ag = g_qh + ((size_t)z << 20) + (size_t)m0 * 256;
    const __half* Bg = g_kh + ((size_t)zk << 20) + (size_t)n0 * 256;

    float acc[4][4][4] = {};
    gemm_core<8>(Ag, Bg, 256, 256, sm, acc);

    const int tid = threadIdx.x, wid = tid >> 5, lane = tid & 31;
    const int wm = wid >> 2, wn = wid & 3;
    const int qr = lane >> 2, qc = lane & 3;

    __half* Ce = g_eh + ((size_t)z << 24);
    const float scale = 0.0625f;
    #pragma unroll
    for (int i = 0; i < 4; i++) {
        int m = m0 + wm * 64 + i * 16 + qr;
        #pragma unroll
        for (int j = 0; j < 4; j++) {
            int n = n0 + wn * 32 + j * 8 + qc * 2;
            __half2 h0 = __floats2half2_rn(__expf(acc[i][j][0] * scale),
                                           __expf(acc[i][j][1] * scale));
            __half2 h1 = __floats2half2_rn(__expf(acc[i][j][2] * scale),
                                           __expf(acc[i][j][3] * scale));
            *(__half2*)(Ce + (size_t)m * 4096 + n)       = h0;
            *(__half2*)(Ce + (size_t)(m + 8) * 4096 + n) = h1;
        }
    }
}

// ---------------------------------------------------------------------------
// Kernel 5: P = E / sum_b E, in place on g_eh. 8 halfs per thread per batch.
// grid 16384 x 256
// ---------------------------------------------------------------------------
__global__ __launch_bounds__(256) void pnorm_kernel() {
    size_t gid = (size_t)blockIdx.x * 256 + threadIdx.x;
    int side = (int)(gid >> 21);
    size_t nm = (gid & 0x1FFFFFull) << 3;
    __half* base = g_eh + (((size_t)side * 4) << 24) + nm;

    uint4 e[BATCH];
    #pragma unroll
    for (int b = 0; b < BATCH; b++) e[b] = *(const uint4*)(base + ((size_t)b << 24));

    #pragma unroll
    for (int t = 0; t < 4; t++) {
        uint32_t* w0 = &((uint32_t*)&e[0])[t];
        uint32_t* w1 = &((uint32_t*)&e[1])[t];
        uint32_t* w2 = &((uint32_t*)&e[2])[t];
        uint32_t* w3 = &((uint32_t*)&e[3])[t];
        float2 f0 = __half22float2(*(__half2*)w0);
        float2 f1 = __half22float2(*(__half2*)w1);
        float2 f2 = __half22float2(*(__half2*)w2);
        float2 f3 = __half22float2(*(__half2*)w3);
        float rx = 1.0f / (f0.x + f1.x + f2.x + f3.x);
        float ry = 1.0f / (f0.y + f1.y + f2.y + f3.y);
        *(__half2*)w0 = __floats2half2_rn(f0.x * rx, f0.y * ry);
        *(__half2*)w1 = __floats2half2_rn(f1.x * rx, f1.y * ry);
        *(__half2*)w2 = __floats2half2_rn(f2.x * rx, f2.y * ry);
        *(__half2*)w3 = __floats2half2_rn(f3.x * rx, f3.y * ry);
    }
    #pragma unroll
    for (int b = 0; b < BATCH; b++) *(uint4*)(base + ((size_t)b << 24)) = e[b];
}

// ---------------------------------------------------------------------------
// Kernel 6: O[z] = P[z] @ V[z].  grid (2, 32, 8), K = 4096
// ---------------------------------------------------------------------------
__global__ __launch_bounds__(256, 2) void pv_mma() {
    extern __shared__ __half sm[];
    const int z = blockIdx.z;
    const int m0 = blockIdx.y << 7, n0 = blockIdx.x << 7;

    const __half* Ag = g_eh  + ((size_t)z << 24) + (size_t)m0 * 4096;
    const __half* Bg = g_vth + ((size_t)z << 20) + (size_t)n0 * 4096;

    float acc[4][4][4] = {};
    gemm_core<128>(Ag, Bg, 4096, 4096, sm, acc);

    const int tid = threadIdx.x, wid = tid >> 5, lane = tid & 31;
    const int wm = wid >> 2, wn = wid & 3;
    const int qr = lane >> 2, qc = lane & 3;

    float* Co = g_o + ((size_t)z << 20);
    #pragma unroll
    for (int i = 0; i < 4; i++) {
        int m = m0 + wm * 64 + i * 16 + qr;
        #pragma unroll
        for (int j = 0; j < 4; j++) {
            int n = n0 + wn * 32 + j * 8 + qc * 2;
            *(float2*)(Co + (size_t)m * 256 + n)       = make_float2(acc[i][j][0], acc[i][j][1]);
            *(float2*)(Co + (size_t)(m + 8) * 256 + n) = make_float2(acc[i][j][2], acc[i][j][3]);
        }
    }
}

// ---------------------------------------------------------------------------
// Kernel 7: out[b,c,p] = x[b,c,p] + (O @ Wo)[b,p,c]  (fp32 FFMA + transpose)
// ---------------------------------------------------------------------------
__global__ __launch_bounds__(256) void gemm_out(const float* __restrict__ Wo,
                                                const float* __restrict__ x,
                                                float* __restrict__ outp,
                                                int side) {
    const float* A = g_o + ((size_t)side << 22);

    int m0 = blockIdx.y << 6, n0 = blockIdx.x << 6;
    __shared__ float As[16][64], Bs[16][64];
    __shared__ float cs[64][65];
    int tid = threadIdx.x;
    int ar = tid >> 2, ac = (tid & 3) << 2;
    int br = tid >> 4, bc = (tid & 15) << 2;
    int tx = tid & 15, ty = tid >> 4;

    float acc[4][4] = {};
    for (int k0 = 0; k0 < 256; k0 += 16) {
        float4 av = *(const float4*)(A + (size_t)(m0 + ar) * 256 + k0 + ac);
        float4 bv = *(const float4*)(Wo + (size_t)(k0 + br) * 256 + n0 + bc);
        __syncthreads();
        As[ac + 0][ar] = av.x; As[ac + 1][ar] = av.y;
        As[ac + 2][ar] = av.z; As[ac + 3][ar] = av.w;
        *(float4*)&Bs[br][bc] = bv;
        __syncthreads();
        #pragma unroll
        for (int k = 0; k < 16; k++) {
            float4 a = *(const float4*)&As[k][ty << 2];
            float4 b4 = *(const float4*)&Bs[k][tx << 2];
            float aa[4] = {a.x, a.y, a.z, a.w};
            float bb[4] = {b4.x, b4.y, b4.z, b4.w};
            #pragma unroll
            for (int i = 0; i < 4; i++)
                #pragma unroll
                for (int j = 0; j < 4; j++)
                    acc[i][j] += aa[i] * bb[j];
        }
    }
    __syncthreads();
    #pragma unroll
    for (int i = 0; i < 4; i++)
        #pragma unroll
        for (int j = 0; j < 4; j++)
            cs[(tx << 2) + j][(ty << 2) + i] = acc[i][j];
    __syncthreads();

    int bb2 = m0 >> 12;
    int p0  = m0 & 4095;
    for (int idx = tid; idx < 64 * 64; idx += 256) {
        int cl = idx >> 6, pl = idx & 63;
        size_t off = ((size_t)bb2 * CH + (n0 + cl)) * HW + (p0 + pl);
        outp[off] = x[off] + cs[cl][pl];
    }
}

// ---------------------------------------------------------------------------
extern "C" void kernel_launch(void* const* d_in, const int* in_sizes, int n_in,
                              void* d_out, int out_size) {
    const float* x_l = (const float*)d_in[0];
    const float* x_r = (const float*)d_in[1];
    const float* Wq  = (const float*)d_in[2];
    const float* Wk  = (const float*)d_in[3];
    const float* Wv  = (const float*)d_in[4];
    const float* Wo  = (const float*)d_in[5];
    const float* g1  = (const float*)d_in[6];
    const float* b1  = (const float*)d_in[7];
    const float* g2  = (const float*)d_in[8];
    const float* b2  = (const float*)d_in[9];
    float* out = (float*)d_out;

    // 1) LayerNorm -> fp16 [p][c], and weight transpose -> fp16
    ln_kernel<<<dim3(HW / 32, BATCH), 256>>>(x_l, g1, b1, 0);
    ln_kernel<<<dim3(HW / 32, BATCH), 256>>>(x_r, g2, b2, 1);
    wconv_kernel<<<768, 256>>>(Wq, Wk, Wv);

    // 2) fused QKV (V transposed)
    qkv_mma<<<dim3(6, 128, 2), 256, SMEM_MMA>>>();

    // 3) E = exp(scale * Q @ K^T)
    scores_mma<<<dim3(32, 32, 8), 256, SMEM_MMA>>>();

    // 4) P = E / sum_b E (in place)
    pnorm_kernel<<<16384, 256>>>();

    // 5) O = P @ V
    pv_mma<<<dim3(2, 32, 8), 256, SMEM_MMA>>>();

    // 6) out = x + (O @ Wo)^T
    gemm_out<<<dim3(4, 256), 256>>>(Wo, x_l, out, 0);
    gemm_out<<<dim3(4, 256), 256>>>(Wo, x_r, out + (size_t)BATCH * CH * HW, 1);
}

// round 4
// speedup vs baseline: 6.5892x; 1.4528x over previous
#include <cuda_runtime.h>
#include <cuda_fp16.h>
#include <cstdint>

#define HW    4096
#define CH    256
#define BATCH 4

// fp16 operands / activations
__device__ __half g_xh [2ull * BATCH * HW * CH];          // LN output [side][p][c]
__device__ __half g_wh [1024ull * 256];                   // [Wq|Wk|Wv|Wo]^T: [n][k]
__device__ __half g_qh [2ull * BATCH * HW * CH];          // [z][p][c]
__device__ __half g_kh [2ull * BATCH * HW * CH];          // [z][p][c]
__device__ __half g_vth[2ull * BATCH * HW * CH];          // V^T: [z][c][m]
__device__ __half g_eh [2ull * BATCH * HW * HW];          // E then P (in place)
__device__ __half g_oh [2ull * BATCH * HW * CH];          // PV output fp16 [side][p][c]

// ---------------------------------------------------------------------------
// low-level helpers
// ---------------------------------------------------------------------------
__device__ __forceinline__ uint32_t smem_u32(const void* p) {
    uint32_t a;
    asm("{ .reg .u64 t; cvta.to.shared.u64 t, %1; cvt.u32.u64 %0, t; }"
        : "=r"(a) : "l"(p));
    return a;
}

__device__ __forceinline__ void mma16816(float (&c)[4], const uint32_t (&a)[4],
                                         uint32_t b0, uint32_t b1) {
    asm volatile(
        "mma.sync.aligned.m16n8k16.row.col.f32.f16.f16.f32 "
        "{%0,%1,%2,%3}, {%4,%5,%6,%7}, {%8,%9}, {%0,%1,%2,%3};"
        : "+f"(c[0]), "+f"(c[1]), "+f"(c[2]), "+f"(c[3])
        : "r"(a[0]), "r"(a[1]), "r"(a[2]), "r"(a[3]), "r"(b0), "r"(b1));
}

__device__ __forceinline__ void ldsm4(uint32_t (&r)[4], uint32_t addr) {
    asm volatile("ldmatrix.sync.aligned.m8n8.x4.shared.b16 {%0,%1,%2,%3}, [%4];"
        : "=r"(r[0]), "=r"(r[1]), "=r"(r[2]), "=r"(r[3]) : "r"(addr));
}

#define CP16(s, g) \
    asm volatile("cp.async.cg.shared.global [%0], [%1], 16;" :: "r"(s), "l"(g))
#define CP_COMMIT() asm volatile("cp.async.commit_group;")
#define CP_WAIT2()  asm volatile("cp.async.wait_group 2;")

// ---------------------------------------------------------------------------
// GEMM core: CTA 128x128, k-chunk 32 halfs, 4-stage cp.async pipeline,
// ldmatrix fragments. 256 threads = 8 warps (2m x 4n), warp tile 64x32.
// smem stage: A 128 rows x 40 halfs + B 128 x 40 = 20480 B; 4 stages = 80 KB.
// ---------------------------------------------------------------------------
#define STG_B   20480
#define SMEM_MMA 81920

template <int NCH>
__device__ __forceinline__ void gemm_core(const __half* __restrict__ Ag,
                                          const __half* __restrict__ Bg,
                                          int ldA, int ldB, uint32_t smb,
                                          float (&acc)[4][4][4]) {
    const int tid  = threadIdx.x;
    const int lane = tid & 31, wid = tid >> 5;
    const int wm = wid >> 2, wn = wid & 3;

    const int lr = tid >> 2;                 // load row 0..63
    const __half* agp = Ag + (size_t)lr * ldA + (tid & 3) * 8;
    const __half* bgp = Bg + (size_t)lr * ldB + (tid & 3) * 8;
    const size_t a64 = (size_t)64 * ldA, b64 = (size_t)64 * ldB;

    const uint32_t sA = smb + lr * 80 + (tid & 3) * 16;
    const uint32_t sB = sA + 10240;

    auto issue = [&](int s, int c) {
        const uint32_t off = s * STG_B;
        const __half* a0 = agp + (size_t)c * 32;
        const __half* b0 = bgp + (size_t)c * 32;
        CP16(sA + off,           a0);
        CP16(sA + off + 64 * 80, a0 + a64);
        CP16(sB + off,           b0);
        CP16(sB + off + 64 * 80, b0 + b64);
        CP_COMMIT();
    };

    issue(0, 0); issue(1, 1); issue(2, 2);

    const uint32_t aBase = smb + (wm * 64 + (lane & 15)) * 80 + (lane >> 4) * 16;
    const uint32_t bBase = smb + 10240 +
        (wn * 32 + (lane & 7) + ((lane >> 4) << 3)) * 80 + ((lane >> 3) & 1) * 16;

    #pragma unroll 1
    for (int c = 0; c < NCH; c++) {
        CP_WAIT2();
        __syncthreads();
        const uint32_t off = (c & 3) * STG_B;
        if (c + 3 < NCH) issue((c + 3) & 3, c + 3);
        else CP_COMMIT();                 // keep group count uniform
        #pragma unroll
        for (int ks = 0; ks < 2; ks++) {
            uint32_t af[4][4], bf[2][4];
            #pragma unroll
            for (int i = 0; i < 4; i++) ldsm4(af[i], aBase + off + i * 16 * 80 + ks * 32);
            #pragma unroll
            for (int p = 0; p < 2; p++) ldsm4(bf[p], bBase + off + p * 16 * 80 + ks * 32);
            #pragma unroll
            for (int i = 0; i < 4; i++)
                #pragma unroll
                for (int j = 0; j < 4; j++)
                    mma16816(acc[i][j], af[i], bf[j >> 1][(j & 1) * 2],
                             bf[j >> 1][(j & 1) * 2 + 1]);
        }
    }
}

// ---------------------------------------------------------------------------
// Kernel 1: LayerNorm over channels with transpose -> fp16 [side][p][c]
// ---------------------------------------------------------------------------
__global__ __launch_bounds__(256) void ln_kernel(const float* __restrict__ x,
                                                 const float* __restrict__ gm,
                                                 const float* __restrict__ bt,
                                                 int side) {
    int b  = blockIdx.y;
    int p0 = blockIdx.x << 5;
    int tid = threadIdx.x, lane = tid & 31, warp = tid >> 5;

    __shared__ float tile[CH][33];
    __shared__ float red[2][8][32];
    __shared__ float mu_s[32], rs_s[32];

    #pragma unroll 4
    for (int i = 0; i < 32; i++) {
        int c = (warp << 5) + i;
        tile[c][lane] = x[((size_t)b * CH + c) * HW + p0 + lane];
    }
    __syncthreads();

    {
        int pl = tid & 31, seg = tid >> 5;
        float s = 0.f, s2 = 0.f;
        #pragma unroll 8
        for (int c = seg * 32; c < seg * 32 + 32; c++) {
            float v = tile[c][pl];
            s += v; s2 += v * v;
        }
        red[0][seg][pl] = s;
        red[1][seg][pl] = s2;
    }
    __syncthreads();
    if (tid < 32) {
        float S = 0.f, S2 = 0.f;
        #pragma unroll
        for (int g = 0; g < 8; g++) { S += red[0][g][tid]; S2 += red[1][g][tid]; }
        float mu  = S * (1.f / 256.f);
        float var = S2 * (1.f / 256.f) - mu * mu;
        mu_s[tid] = mu;
        rs_s[tid] = rsqrtf(var + 1e-5f);
    }
    __syncthreads();

    __half* xh = g_xh + ((size_t)side << 22);
    #pragma unroll
    for (int pp = warp * 4; pp < warp * 4 + 4; pp++) {
        float mu = mu_s[pp], rs = rs_s[pp];
        #pragma unroll
        for (int c = lane; c < CH; c += 32) {
            float v = (tile[c][pp] - mu) * rs * gm[c] + bt[c];
            xh[((size_t)(b * HW + p0 + pp)) * 256 + c] = __float2half_rn(v);
        }
    }
}

// ---------------------------------------------------------------------------
// Kernel 2: weight transpose+convert: g_wh[n][k] = W[k][n], 4 matrices
// ---------------------------------------------------------------------------
__global__ __launch_bounds__(256) void wconv_kernel(const float* __restrict__ Wq,
                                                    const float* __restrict__ Wk,
                                                    const float* __restrict__ Wv,
                                                    const float* __restrict__ Wo) {
    int n = blockIdx.x, k = threadIdx.x;
    const float* W = (n < 256) ? Wq : (n < 512) ? Wk : (n < 768) ? Wv : Wo;
    g_wh[(size_t)n * 256 + k] = __float2half_rn(W[(size_t)k * 256 + (n & 255)]);
}

// ---------------------------------------------------------------------------
// Kernel 3: fused QKV GEMM. grid (6, 128, 2). N: [0,256)Q [256,512)K [512,768)V
// ---------------------------------------------------------------------------
__global__ __launch_bounds__(256, 2) void qkv_mma() {
    extern __shared__ char smraw[];
    const uint32_t smb = smem_u32(smraw);
    const int side = blockIdx.z;
    const int m0 = blockIdx.y << 7, n0 = blockIdx.x << 7;

    const __half* Ag = g_xh + ((size_t)side << 22) + (size_t)m0 * 256;
    const __half* Bg = g_wh + (size_t)n0 * 256;

    float acc[4][4][4] = {};
    gemm_core<8>(Ag, Bg, 256, 256, smb, acc);

    const int tid = threadIdx.x, wid = tid >> 5, lane = tid & 31;
    const int wm = wid >> 2, wn = wid & 3;
    const int qr = lane >> 2, qc = lane & 3;

    const int z  = side * 4 + (m0 >> 12);
    const int pb = m0 & 4095;

    if (n0 < 512) {
        __half* dst = ((n0 >> 8) == 0 ? g_qh : g_kh) + ((size_t)z << 20);
        const int nloc = n0 & 255;
        #pragma unroll
        for (int i = 0; i < 4; i++) {
            int p = pb + wm * 64 + i * 16 + qr;
            #pragma unroll
            for (int j = 0; j < 4; j++) {
                int col = nloc + wn * 32 + j * 8 + qc * 2;
                *(__half2*)(dst + (size_t)p * 256 + col) =
                    __floats2half2_rn(acc[i][j][0], acc[i][j][1]);
                *(__half2*)(dst + (size_t)(p + 8) * 256 + col) =
                    __floats2half2_rn(acc[i][j][2], acc[i][j][3]);
            }
        }
    } else {
        // V: transpose via smem -> g_vth[z][c][m]
        __syncthreads();
        __half* st = (__half*)smraw;   // [128 n][136 m]
        #pragma unroll
        for (int i = 0; i < 4; i++) {
            int ml = wm * 64 + i * 16 + qr;
            #pragma unroll
            for (int j = 0; j < 4; j++) {
                int nl = wn * 32 + j * 8 + qc * 2;
                st[(size_t)nl * 136 + ml]           = __float2half_rn(acc[i][j][0]);
                st[(size_t)(nl + 1) * 136 + ml]     = __float2half_rn(acc[i][j][1]);
                st[(size_t)nl * 136 + ml + 8]       = __float2half_rn(acc[i][j][2]);
                st[(size_t)(nl + 1) * 136 + ml + 8] = __float2half_rn(acc[i][j][3]);
            }
        }
        __syncthreads();
        const int cv0 = n0 - 512;
        __half* dst = g_vth + ((size_t)z << 20) + pb;
        for (int idx = tid; idx < 128 * 16; idx += 256) {
            int r = idx >> 4, g = idx & 15;
            uint4 v = *(const uint4*)(st + (size_t)r * 136 + g * 8);
            *(uint4*)(dst + (size_t)(cv0 + r) * 4096 + g * 8) = v;
        }
    }
}

// ---------------------------------------------------------------------------
// Kernel 4: scores  E[z,m,n] = exp(scale * Q[z][m] . K[z'][n]) -> fp16
// grid (32, 32, 8)
// ---------------------------------------------------------------------------
__global__ __launch_bounds__(256, 2) void scores_mma() {
    extern __shared__ char smraw[];
    const uint32_t smb = smem_u32(smraw);
    const int z = blockIdx.z;
    const int zk = ((z >> 2) ^ 1) * 4 + (z & 3);
    const int m0 = blockIdx.y << 7, n0 = blockIdx.x << 7;

    const __half* Ag = g_qh + ((size_t)z << 20) + (size_t)m0 * 256;
    const __half* Bg = g_kh + ((size_t)zk << 20) + (size_t)n0 * 256;

    float acc[4][4][4] = {};
    gemm_core<8>(Ag, Bg, 256, 256, smb, acc);

    const int tid = threadIdx.x, wid = tid >> 5, lane = tid & 31;
    const int wm = wid >> 2, wn = wid & 3;
    const int qr = lane >> 2, qc = lane & 3;

    __half* Ce = g_eh + ((size_t)z << 24);
    const float scale = 0.0625f;
    #pragma unroll
    for (int i = 0; i < 4; i++) {
        int m = m0 + wm * 64 + i * 16 + qr;
        #pragma unroll
        for (int j = 0; j < 4; j++) {
            int n = n0 + wn * 32 + j * 8 + qc * 2;
            *(__half2*)(Ce + (size_t)m * 4096 + n) =
                __floats2half2_rn(__expf(acc[i][j][0] * scale),
                                  __expf(acc[i][j][1] * scale));
            *(__half2*)(Ce + (size_t)(m + 8) * 4096 + n) =
                __floats2half2_rn(__expf(acc[i][j][2] * scale),
                                  __expf(acc[i][j][3] * scale));
        }
    }
}

// ---------------------------------------------------------------------------
// Kernel 5: P = E / sum_b E, in place on g_eh
// ---------------------------------------------------------------------------
__global__ __launch_bounds__(256) void pnorm_kernel() {
    size_t gid = (size_t)blockIdx.x * 256 + threadIdx.x;
    int side = (int)(gid >> 21);
    size_t nm = (gid & 0x1FFFFFull) << 3;
    __half* base = g_eh + (((size_t)side * 4) << 24) + nm;

    uint4 e[BATCH];
    #pragma unroll
    for (int b = 0; b < BATCH; b++) e[b] = *(const uint4*)(base + ((size_t)b << 24));

    #pragma unroll
    for (int t = 0; t < 4; t++) {
        uint32_t* w0 = &((uint32_t*)&e[0])[t];
        uint32_t* w1 = &((uint32_t*)&e[1])[t];
        uint32_t* w2 = &((uint32_t*)&e[2])[t];
        uint32_t* w3 = &((uint32_t*)&e[3])[t];
        float2 f0 = __half22float2(*(__half2*)w0);
        float2 f1 = __half22float2(*(__half2*)w1);
        float2 f2 = __half22float2(*(__half2*)w2);
        float2 f3 = __half22float2(*(__half2*)w3);
        float rx = 1.0f / (f0.x + f1.x + f2.x + f3.x);
        float ry = 1.0f / (f0.y + f1.y + f2.y + f3.y);
        *(__half2*)w0 = __floats2half2_rn(f0.x * rx, f0.y * ry);
        *(__half2*)w1 = __floats2half2_rn(f1.x * rx, f1.y * ry);
        *(__half2*)w2 = __floats2half2_rn(f2.x * rx, f2.y * ry);
        *(__half2*)w3 = __floats2half2_rn(f3.x * rx, f3.y * ry);
    }
    #pragma unroll
    for (int b = 0; b < BATCH; b++) *(uint4*)(base + ((size_t)b << 24)) = e[b];
}

// ---------------------------------------------------------------------------
// Kernel 6: O[z] = P[z] @ V[z] -> fp16.  grid (2, 32, 8), K = 4096
// ---------------------------------------------------------------------------
__global__ __launch_bounds__(256, 2) void pv_mma() {
    extern __shared__ char smraw[];
    const uint32_t smb = smem_u32(smraw);
    const int z = blockIdx.z;
    const int m0 = blockIdx.y << 7, n0 = blockIdx.x << 7;

    const __half* Ag = g_eh  + ((size_t)z << 24) + (size_t)m0 * 4096;
    const __half* Bg = g_vth + ((size_t)z << 20) + (size_t)n0 * 4096;

    float acc[4][4][4] = {};
    gemm_core<128>(Ag, Bg, 4096, 4096, smb, acc);

    const int tid = threadIdx.x, wid = tid >> 5, lane = tid & 31;
    const int wm = wid >> 2, wn = wid & 3;
    const int qr = lane >> 2, qc = lane & 3;

    __half* Co = g_oh + ((size_t)z << 20);
    #pragma unroll
    for (int i = 0; i < 4; i++) {
        int m = m0 + wm * 64 + i * 16 + qr;
        #pragma unroll
        for (int j = 0; j < 4; j++) {
            int n = n0 + wn * 32 + j * 8 + qc * 2;
            *(__half2*)(Co + (size_t)m * 256 + n) =
                __floats2half2_rn(acc[i][j][0], acc[i][j][1]);
            *(__half2*)(Co + (size_t)(m + 8) * 256 + n) =
                __floats2half2_rn(acc[i][j][2], acc[i][j][3]);
        }
    }
}

// ---------------------------------------------------------------------------
// Kernel 7: out[b,c,p] = x[b,c,p] + (O @ Wo)[b,p,c]   (fp16 MMA + transpose)
// grid (2, 128, 2)
// ---------------------------------------------------------------------------
__global__ __launch_bounds__(256, 2) void out_mma(const float* __restrict__ xl,
                                                  const float* __restrict__ xr,
                                                  float* __restrict__ outp) {
    extern __shared__ char smraw[];
    const uint32_t smb = smem_u32(smraw);
    const int side = blockIdx.z;
    const int m0 = blockIdx.y << 7, n0 = blockIdx.x << 7;

    const __half* Ag = g_oh + ((size_t)side << 22) + (size_t)m0 * 256;
    const __half* Bg = g_wh + (size_t)(768 + n0) * 256;

    float acc[4][4][4] = {};
    gemm_core<8>(Ag, Bg, 256, 256, smb, acc);

    const int tid = threadIdx.x, wid = tid >> 5, lane = tid & 31;
    const int wm = wid >> 2, wn = wid & 3;
    const int qr = lane >> 2, qc = lane & 3;

    __syncthreads();
    float* st = (float*)smraw;   // [128 m][129]
    #pragma unroll
    for (int i = 0; i < 4; i++) {
        int ml = wm * 64 + i * 16 + qr;
        #pragma unroll
        for (int j = 0; j < 4; j++) {
            int nl = wn * 32 + j * 8 + qc * 2;
            st[(size_t)ml * 129 + nl]           = acc[i][j][0];
            st[(size_t)ml * 129 + nl + 1]       = acc[i][j][1];
            st[(size_t)(ml + 8) * 129 + nl]     = acc[i][j][2];
            st[(size_t)(ml + 8) * 129 + nl + 1] = acc[i][j][3];
        }
    }
    __syncthreads();

    const float* x = side ? xr : xl;
    float* op = outp + ((size_t)side << 22);
    const int b = m0 >> 12, p0 = m0 & 4095;
    for (int idx = tid; idx < 128 * 128; idx += 256) {
        int cl = idx >> 7, pl = idx & 127;
        size_t off = ((size_t)b * 256 + n0 + cl) * 4096 + p0 + pl;
        op[off] = x[off] + st[(size_t)pl * 129 + cl];
    }
}

// ---------------------------------------------------------------------------
extern "C" void kernel_launch(void* const* d_in, const int* in_sizes, int n_in,
                              void* d_out, int out_size) {
    const float* x_l = (const float*)d_in[0];
    const float* x_r = (const float*)d_in[1];
    const float* Wq  = (const float*)d_in[2];
    const float* Wk  = (const float*)d_in[3];
    const float* Wv  = (const float*)d_in[4];
    const float* Wo  = (const float*)d_in[5];
    const float* g1  = (const float*)d_in[6];
    const float* b1  = (const float*)d_in[7];
    const float* g2  = (const float*)d_in[8];
    const float* b2  = (const float*)d_in[9];
    float* out = (float*)d_out;

    static bool attr_done = false;
    if (!attr_done) {
        cudaFuncSetAttribute(qkv_mma,    cudaFuncAttributeMaxDynamicSharedMemorySize, SMEM_MMA);
        cudaFuncSetAttribute(scores_mma, cudaFuncAttributeMaxDynamicSharedMemorySize, SMEM_MMA);
        cudaFuncSetAttribute(pv_mma,     cudaFuncAttributeMaxDynamicSharedMemorySize, SMEM_MMA);
        cudaFuncSetAttribute(out_mma,    cudaFuncAttributeMaxDynamicSharedMemorySize, SMEM_MMA);
        attr_done = true;
    }

    // 1) LayerNorm -> fp16 [p][c], weights -> fp16 [n][k]
    ln_kernel<<<dim3(HW / 32, BATCH), 256>>>(x_l, g1, b1, 0);
    ln_kernel<<<dim3(HW / 32, BATCH), 256>>>(x_r, g2, b2, 1);
    wconv_kernel<<<1024, 256>>>(Wq, Wk, Wv, Wo);

    // 2) fused QKV (V transposed)
    qkv_mma<<<dim3(6, 128, 2), 256, SMEM_MMA>>>();

    // 3) E = exp(scale * Q @ K^T)
    scores_mma<<<dim3(32, 32, 8), 256, SMEM_MMA>>>();

    // 4) P = E / sum_b E (in place)
    pnorm_kernel<<<16384, 256>>>();

    // 5) O = P @ V -> fp16
    pv_mma<<<dim3(2, 32, 8), 256, SMEM_MMA>>>();

    // 6) out = x + (O @ Wo)^T
    out_mma<<<dim3(2, 128, 2), 256, SMEM_MMA>>>(x_l, x_r, out);
}